// round 14
// baseline (speedup 1.0000x reference)
#include <cuda_runtime.h>
#include <cuda_fp16.h>
#include <math.h>
#include <stdint.h>

#define Bv 4
#define Vv 8
#define HW 16384
#define VP 7
#define NBJ 28
#define NIMG 32
typedef unsigned long long u64;
typedef uint32_t u32;

// ------------------------- device scratch -------------------------
__device__ __half g_fh[NIMG*HW*64];   // fused features fp16, NHWC
__device__ __half g_mh[NIMG*HW*64];   // gelu(conv1) fp16, NHWC
__device__ __half g_wh[2*9*64*64];    // [layer][tap][ic][oc] fp16
__device__ int   g_src[NBJ*HW];
__device__ int   g_cnt[NBJ];

// ------------------------- PTX helpers -------------------------
__device__ __forceinline__ u32 s2u(const void* p) {
    u32 a;
    asm("{ .reg .u64 t; cvta.to.shared.u64 t, %1; cvt.u32.u64 %0, t; }" : "=r"(a) : "l"(p));
    return a;
}
__device__ __forceinline__ void ldsm4(u32* r, u32 addr) {
    asm volatile("ldmatrix.sync.aligned.m8n8.x4.shared.b16 {%0,%1,%2,%3}, [%4];"
        : "=r"(r[0]), "=r"(r[1]), "=r"(r[2]), "=r"(r[3]) : "r"(addr));
}
__device__ __forceinline__ void ldsm4t(u32* r, u32 addr) {
    asm volatile("ldmatrix.sync.aligned.m8n8.x4.trans.shared.b16 {%0,%1,%2,%3}, [%4];"
        : "=r"(r[0]), "=r"(r[1]), "=r"(r[2]), "=r"(r[3]) : "r"(addr));
}
__device__ __forceinline__ void mma_fp16(float* d, const u32* a, const u32* b) {
    asm volatile("mma.sync.aligned.m16n8k16.row.col.f32.f16.f16.f32 "
        "{%0,%1,%2,%3}, {%4,%5,%6,%7}, {%8,%9}, {%0,%1,%2,%3};"
        : "+f"(d[0]), "+f"(d[1]), "+f"(d[2]), "+f"(d[3])
        : "r"(a[0]), "r"(a[1]), "r"(a[2]), "r"(a[3]), "r"(b[0]), "r"(b[1]));
}
__device__ __forceinline__ void cp_async16(u32 smem, const void* gptr, int szbytes) {
    asm volatile("cp.async.cg.shared.global [%0], [%1], 16, %2;"
        :: "r"(smem), "l"(gptr), "r"(szbytes) : "memory");
}
#define CP_COMMIT() asm volatile("cp.async.commit_group;" ::: "memory")
#define CP_WAIT0()  asm volatile("cp.async.wait_group 0;" ::: "memory")

// ---------------------------------------------------------------------------
// Kernel 1: geometry (count, camera inline) + weight fp16 convert, one launch.
// ---------------------------------------------------------------------------
__global__ void k_pre(const float* __restrict__ means,
                      const float* __restrict__ intr, const float* __restrict__ extr,
                      const float* __restrict__ w1, const float* __restrict__ w2)
{
    int bid = blockIdx.x;
    if (bid >= 112) {
        int idx = (bid - 112)*256 + threadIdx.x;   // < 73728 exactly
        int layer = idx / 36864; int rem = idx - layer*36864;
        int tap = rem >> 12;
        int ic = (rem >> 6) & 63, oc = rem & 63;
        const float* w = layer ? w2 : w1;
        g_wh[idx] = __float2half(w[(oc*64 + ic)*9 + tap]);
        return;
    }
    int bj = bid >> 2, seg = bid & 3;
    int b = bj / VP, j = bj % VP, k = j + 1;
    __shared__ float cm[24];
    __shared__ int s_cnt;
    if (threadIdx.x == 0) {
        const float* E = extr + (b*Vv + k)*16;
        const float* K = intr + (b*Vv + k)*9;
        float m[16], inv[16];
        #pragma unroll
        for (int i = 0; i < 16; ++i) m[i] = E[i];
        inv[0]  =  m[5]*m[10]*m[15] - m[5]*m[11]*m[14] - m[9]*m[6]*m[15] + m[9]*m[7]*m[14] + m[13]*m[6]*m[11] - m[13]*m[7]*m[10];
        inv[4]  = -m[4]*m[10]*m[15] + m[4]*m[11]*m[14] + m[8]*m[6]*m[15] - m[8]*m[7]*m[14] - m[12]*m[6]*m[11] + m[12]*m[7]*m[10];
        inv[8]  =  m[4]*m[9]*m[15]  - m[4]*m[11]*m[13] - m[8]*m[5]*m[15] + m[8]*m[7]*m[13] + m[12]*m[5]*m[11] - m[12]*m[7]*m[9];
        inv[12] = -m[4]*m[9]*m[14]  + m[4]*m[10]*m[13] + m[8]*m[5]*m[14] - m[8]*m[6]*m[13] - m[12]*m[5]*m[10] + m[12]*m[6]*m[9];
        inv[1]  = -m[1]*m[10]*m[15] + m[1]*m[11]*m[14] + m[9]*m[2]*m[15] - m[9]*m[3]*m[14] - m[13]*m[2]*m[11] + m[13]*m[3]*m[10];
        inv[5]  =  m[0]*m[10]*m[15] - m[0]*m[11]*m[14] - m[8]*m[2]*m[15] + m[8]*m[3]*m[14] + m[12]*m[2]*m[11] - m[12]*m[3]*m[10];
        inv[9]  = -m[0]*m[9]*m[15]  + m[0]*m[11]*m[13] + m[8]*m[1]*m[15] - m[8]*m[3]*m[13] - m[12]*m[1]*m[11] + m[12]*m[3]*m[9];
        inv[13] =  m[0]*m[9]*m[14]  - m[0]*m[10]*m[13] - m[8]*m[1]*m[14] + m[8]*m[2]*m[13] + m[12]*m[1]*m[10] - m[12]*m[2]*m[9];
        inv[2]  =  m[1]*m[6]*m[15]  - m[1]*m[7]*m[14]  - m[5]*m[2]*m[15] + m[5]*m[3]*m[14] + m[13]*m[2]*m[7]  - m[13]*m[3]*m[6];
        inv[6]  = -m[0]*m[6]*m[15]  + m[0]*m[7]*m[14]  + m[4]*m[2]*m[15] - m[4]*m[3]*m[14] - m[12]*m[2]*m[7]  + m[12]*m[3]*m[6];
        inv[10] =  m[0]*m[5]*m[15]  - m[0]*m[7]*m[13]  - m[4]*m[1]*m[15] + m[4]*m[3]*m[13] + m[12]*m[1]*m[7]  - m[12]*m[3]*m[5];
        inv[14] = -m[0]*m[5]*m[14]  + m[0]*m[6]*m[13]  + m[4]*m[1]*m[14] - m[4]*m[2]*m[13] - m[12]*m[1]*m[6]  + m[12]*m[2]*m[5];
        inv[3]  = -m[1]*m[6]*m[11]  + m[1]*m[7]*m[10]  + m[5]*m[2]*m[11] - m[5]*m[3]*m[10] - m[9]*m[2]*m[7]   + m[9]*m[3]*m[6];
        inv[7]  =  m[0]*m[6]*m[11]  - m[0]*m[7]*m[10]  - m[4]*m[2]*m[11] + m[4]*m[3]*m[10] + m[8]*m[2]*m[7]   - m[8]*m[3]*m[6];
        inv[11] = -m[0]*m[5]*m[11]  + m[0]*m[7]*m[9]   + m[4]*m[1]*m[11] - m[4]*m[3]*m[9]  - m[8]*m[1]*m[7]   + m[8]*m[3]*m[5];
        inv[15] =  m[0]*m[5]*m[10]  - m[0]*m[6]*m[9]   - m[4]*m[1]*m[10] + m[4]*m[2]*m[9]  + m[8]*m[1]*m[6]   - m[8]*m[2]*m[5];
        float det = m[0]*inv[0] + m[1]*inv[4] + m[2]*inv[8] + m[3]*inv[12];
        float id = 1.0f / det;
        #pragma unroll
        for (int i = 0; i < 12; ++i) cm[i] = inv[i]*id;
        #pragma unroll
        for (int i = 0; i < 9; ++i) cm[12 + i] = K[i];
        s_cnt = 0;
    }
    __syncthreads();
    const float* mb = means + (size_t)(b*Vv + j)*HW*3;
    int cnt = 0;
    int i0 = seg * 4096;
    for (int i = i0 + threadIdx.x; i < i0 + 4096; i += blockDim.x) {
        float x = mb[i*3+0], y = mb[i*3+1], z = mb[i*3+2];
        float c0 = __fadd_rn(__fadd_rn(__fadd_rn(__fmul_rn(cm[0],x), __fmul_rn(cm[1],y)), __fmul_rn(cm[2],z)), cm[3]);
        float c1 = __fadd_rn(__fadd_rn(__fadd_rn(__fmul_rn(cm[4],x), __fmul_rn(cm[5],y)), __fmul_rn(cm[6],z)), cm[7]);
        float c2 = __fadd_rn(__fadd_rn(__fadd_rn(__fmul_rn(cm[8],x), __fmul_rn(cm[9],y)), __fmul_rn(cm[10],z)), cm[11]);
        float p0 = __fadd_rn(__fadd_rn(__fmul_rn(cm[12],c0), __fmul_rn(cm[13],c1)), __fmul_rn(cm[14],c2));
        float p1 = __fadd_rn(__fadd_rn(__fmul_rn(cm[15],c0), __fmul_rn(cm[16],c1)), __fmul_rn(cm[17],c2));
        float p2 = __fadd_rn(__fadd_rn(__fmul_rn(cm[18],c0), __fmul_rn(cm[19],c1)), __fmul_rn(cm[20],c2));
        float d  = __fadd_rn(p2, 1e-8f);
        float nx = p0 / d, ny = p1 / d;
        bool valid = (nx >= 0.f) && (nx < 1.f) && (ny >= 0.f) && (ny < 1.f) && (c2 > 1e-8f);
        int px = (int)floorf(__fmul_rn(nx, 128.f)); px = min(max(px, 0), 127);
        int py = (int)floorf(__fmul_rn(ny, 128.f)); py = min(max(py, 0), 127);
        g_src[bj*HW + i] = valid ? (py*128 + px) : -1;
        cnt += valid ? 1 : 0;
    }
    atomicAdd(&s_cnt, cnt);
    __syncthreads();
    if (threadIdx.x == 0) atomicAdd(&g_cnt[bj], s_cnt);
}

// ---------------------------------------------------------------------------
// Kernel 2: fuse -> NHWC fp16 (unchanged numerics)
// ---------------------------------------------------------------------------
__global__ __launch_bounds__(256)
void k_fuse2(const float* __restrict__ gsf)
{
    int y = blockIdx.x, n = blockIdx.y;
    int b = n >> 3, view = n & 7;
    __shared__ int S[128];
    __shared__ float s_w;
    int tid = threadIdx.x;
    if (view < VP) {
        int bj = b*VP + view;
        if (tid < 128) S[tid] = g_src[bj*HW + y*128 + tid];
        if (tid == 0) s_w = (0.1f / (float)HW) * (float)g_cnt[bj];
    } else {
        if (tid < 128) S[tid] = -1;
        if (tid == 0) s_w = 0.f;
    }
    __syncthreads();
    float wg = s_w, iw = 1.f / (1.f + wg);
    const float* fj = gsf + ((size_t)n*HW + (size_t)y*128)*64;
    const float* fk = gsf + (size_t)(n+1)*HW*64;
    size_t ob = ((size_t)n*HW + (size_t)y*128)*64;
    #pragma unroll
    for (int i = 0; i < 8; ++i) {
        int idx = tid + i*256;
        int px = idx >> 4, c4 = (idx & 15)*4;
        float4 a = *(const float4*)(fj + px*64 + c4);
        int s = S[px];
        float4 g = make_float4(0.f,0.f,0.f,0.f);
        if (s >= 0) g = *(const float4*)(fk + (size_t)s*64 + c4);
        float v0 = (a.x + g.x*wg)*iw, v1 = (a.y + g.y*wg)*iw;
        float v2 = (a.z + g.z*wg)*iw, v3 = (a.w + g.w*wg)*iw;
        uint2 ph;
        ph.x = (u32)__half_as_ushort(__float2half(v0)) | ((u32)__half_as_ushort(__float2half(v1)) << 16);
        ph.y = (u32)__half_as_ushort(__float2half(v2)) | ((u32)__half_as_ushort(__float2half(v3)) << 16);
        *(uint2*)(g_fh + ob + px*64 + c4) = ph;
    }
}

// ---------------------------------------------------------------------------
// Kernel 3/4: mma.sync fp16 single-term conv, QUAD-row iterations, 9-slot ring.
// grid(2 ochalf, 2 slab, 32 img), 256 threads = 8 warps,
// warp tile 16px x 32oc x 4 rows. Per-accumulator MMA order (dx->kc->dy)
// unchanged => output bit-identical to R11/R12.
// Ring discipline: compute reads rows gy-1..gy+4 (6 slots). Rows gy+5..gy+7
// stage pre-compute (their slots mod 9 are dead); row gy+8 shares the slot of
// row gy-1 and stages after the mid-barrier, overlapping the epilogue.
// SMEM: B 9 tiles [64ic x 32oc] stride 80B = 46080B;
//       A ring 9 slots x [130 entries x 64ic] stride 144B = 168480B.
// Total 214560B -> 1 block/SM.
// ---------------------------------------------------------------------------
#define BTILE 5120u
#define AROW 144u
#define ASLOT 18720u
#define BOFF_SZ 46080u
#define SMEM_REQ 214560

template<bool FIRST>
__global__ void __launch_bounds__(256, 1) k_conv_mma(
    const __half* __restrict__ inh, const float* __restrict__ bias,
    __half* __restrict__ outh, float* __restrict__ outf,
    const __half* __restrict__ wh)
{
    extern __shared__ char dsm[];
    u32 sb = s2u(dsm);
    u32 Boff = sb, Aoff = sb + BOFF_SZ;

    int ochalf = blockIdx.x, slab = blockIdx.y, n = blockIdx.z;
    int oc0 = ochalf*32, ybase = slab*64;
    int tid = threadIdx.x, wid = tid >> 5, t = tid & 31;
    int px0 = wid*16;

    // ---- B build: 9 tap tiles, stride-80 rows (2304 chunks) ----
    #pragma unroll
    for (int i = 0; i < 9; ++i) {
        int c = tid + i*256;
        int tap = c >> 8;
        int rem = c & 255;
        int ic = rem >> 2, q = rem & 3;
        uint4 v = *(const uint4*)(wh + ((size_t)tap*64 + ic)*64 + oc0 + q*8);
        *(uint4*)(dsm + (u32)tap*BTILE + (u32)ic*80u + (u32)q*16u) = v;
    }
    // ---- prologue: build rows ybase-1 .. ybase+4 (1040 chunks each) ----
    for (int r = ybase-1; r <= ybase+4; ++r) {
        int slot = (r + 9) % 9;
        u32 base = BOFF_SZ + (u32)slot*ASLOT;
        bool vr = ((unsigned)r < 128u);
        #pragma unroll
        for (int i = 0; i < 5; ++i) {
            int c = tid + i*256;
            if (c < 1040) {
                int e = c >> 3, q = c & 7;       // entry 0..129
                int gpx = e - 1;
                uint4 v = make_uint4(0,0,0,0);
                if (vr && (unsigned)gpx < 128u)
                    v = *(const uint4*)(inh + ((size_t)n*HW + (size_t)r*128 + gpx)*64 + q*8);
                *(uint4*)(dsm + base + (u32)e*AROW + (u32)q*16u) = v;
            }
        }
    }
    // per-thread bias regs
    float bo0[4], bo1[4];
    #pragma unroll
    for (int nb = 0; nb < 4; ++nb) {
        int oc = oc0 + nb*8 + (t & 3)*2;
        bo0[nb] = bias[oc];
        bo1[nb] = bias[oc + 1];
    }
    __syncthreads();

    u32 laneA = (u32)(t & 15)*AROW + (u32)((t >> 4) << 4);
    u32 laneB = (u32)(t & 15)*80u  + (u32)((t >> 4) << 4);

    #pragma unroll 1
    for (int it = 0; it < 16; ++it) {
        int gy = ybase + it*4;
        // ---- pre-stage rows gy+5..gy+7 (slots are dead) ----
        #pragma unroll
        for (int rr = 0; rr < 3; ++rr) {
            int r = gy + 5 + rr;
            bool vr = (r <= 127);
            int rc = vr ? r : 127;
            u32 base = Aoff + (u32)((r + 9) % 9)*ASLOT;
            const __half* gsrc = inh + ((size_t)n*HW + (size_t)rc*128)*64;
            #pragma unroll
            for (int i = 0; i < 5; ++i) {
                int c = tid + i*256;
                if (c < 1040) {
                    int e = c >> 3, q = c & 7;
                    int gpx = e - 1;
                    bool vp = ((unsigned)gpx < 128u);
                    int gpxc = vp ? gpx : 0;
                    cp_async16(base + (u32)e*AROW + (u32)q*16u,
                               gsrc + (size_t)gpxc*64 + q*8, (vr && vp) ? 16 : 0);
                }
            }
        }
        CP_COMMIT();
        // ---- compute rows gy .. gy+3 ----
        float acc[4][4][4];
        #pragma unroll
        for (int r = 0; r < 4; ++r)
            #pragma unroll
            for (int nb = 0; nb < 4; ++nb)
                #pragma unroll
                for (int i = 0; i < 4; ++i) acc[r][nb][i] = 0.f;

        u32 abase[6];
        #pragma unroll
        for (int j = 0; j < 6; ++j)
            abase[j] = Aoff + (u32)((gy - 1 + j + 9) % 9)*ASLOT;

        #pragma unroll
        for (int dx = 0; dx < 3; ++dx) {
            #pragma unroll
            for (int kc = 0; kc < 4; ++kc) {
                u32 B[3][8];
                #pragma unroll
                for (int dy = 0; dy < 3; ++dy) {
                    u32 bb = Boff + (u32)(dy*3 + dx)*BTILE + laneB + (u32)kc*1280u;
                    ldsm4t(B[dy],     bb);
                    ldsm4t(B[dy] + 4, bb + 32u);
                }
                u32 Afr[6][4];
                #pragma unroll
                for (int j = 0; j < 6; ++j)
                    ldsm4(Afr[j], abase[j] + (u32)(px0 + dx)*AROW + laneA + (u32)kc*32u);
                #pragma unroll
                for (int outr = 0; outr < 4; ++outr) {
                    #pragma unroll
                    for (int dy = 0; dy < 3; ++dy) {
                        #pragma unroll
                        for (int nb = 0; nb < 4; ++nb)
                            mma_fp16(acc[outr][nb], Afr[outr + dy], &B[dy][nb*2]);
                    }
                }
            }
        }
        // ---- mid barrier: all warps done reading slot of row gy-1 ----
        __syncthreads();
        // ---- post-stage row gy+8 into slot of row gy-1, overlaps epilogue ----
        {
            int r = gy + 8;
            bool vr = (r <= 127);
            int rc = vr ? r : 127;
            u32 base = Aoff + (u32)((r + 9) % 9)*ASLOT;
            const __half* gsrc = inh + ((size_t)n*HW + (size_t)rc*128)*64;
            #pragma unroll
            for (int i = 0; i < 5; ++i) {
                int c = tid + i*256;
                if (c < 1040) {
                    int e = c >> 3, q = c & 7;
                    int gpx = e - 1;
                    bool vp = ((unsigned)gpx < 128u);
                    int gpxc = vp ? gpx : 0;
                    cp_async16(base + (u32)e*AROW + (u32)q*16u,
                               gsrc + (size_t)gpxc*64 + q*8, (vr && vp) ? 16 : 0);
                }
            }
            CP_COMMIT();
        }
        // ---- epilogue: bias (+gelu), store rows gy..gy+3 ----
        #pragma unroll
        for (int r = 0; r < 4; ++r) {
            int gyr = gy + r;
            #pragma unroll
            for (int nb = 0; nb < 4; ++nb) {
                int oc = oc0 + nb*8 + (t & 3)*2;
                #pragma unroll
                for (int rg = 0; rg < 2; ++rg) {
                    int px = px0 + (t >> 2) + rg*8;
                    float v0 = acc[r][nb][rg*2]   + bo0[nb];
                    float v1 = acc[r][nb][rg*2+1] + bo1[nb];
                    size_t base = ((size_t)n*HW + (size_t)gyr*128 + px)*64 + oc;
                    if (FIRST) {
                        v0 = 0.5f * v0 * (1.0f + erff(v0 * 0.70710678118654752f));
                        v1 = 0.5f * v1 * (1.0f + erff(v1 * 0.70710678118654752f));
                        u32 hp = (u32)__half_as_ushort(__float2half(v0))
                               | ((u32)__half_as_ushort(__float2half(v1)) << 16);
                        *(u32*)(outh + base) = hp;
                    } else {
                        *(float2*)(outf + base) = make_float2(v0, v1);
                    }
                }
            }
        }
        // ---- wait staged rows, barrier ----
        CP_WAIT0();
        __syncthreads();
    }
}

// ---------------------------------------------------------------------------
extern "C" void kernel_launch(void* const* d_in, const int* in_sizes, int n_in,
                              void* d_out, int out_size)
{
    const float* means = (const float*)d_in[0];
    const float* gsf   = (const float*)d_in[2];
    const float* intr  = (const float*)d_in[3];
    const float* extr  = (const float*)d_in[4];
    const float* w1    = (const float*)d_in[5];
    const float* b1    = (const float*)d_in[6];
    const float* w2    = (const float*)d_in[7];
    const float* b2    = (const float*)d_in[8];
    float* out = (float*)d_out;

    __half *pfh, *pmh, *pwh;
    int* pcnt;
    cudaGetSymbolAddress((void**)&pfh, g_fh);
    cudaGetSymbolAddress((void**)&pmh, g_mh);
    cudaGetSymbolAddress((void**)&pwh, g_wh);
    cudaGetSymbolAddress((void**)&pcnt, g_cnt);

    cudaFuncSetAttribute(k_conv_mma<true>,  cudaFuncAttributeMaxDynamicSharedMemorySize, SMEM_REQ);
    cudaFuncSetAttribute(k_conv_mma<false>, cudaFuncAttributeMaxDynamicSharedMemorySize, SMEM_REQ);

    cudaMemsetAsync(pcnt, 0, NBJ*sizeof(int), 0);
    k_pre<<<400, 256>>>(means, intr, extr, w1, w2);
    k_fuse2<<<dim3(128, 32), 256>>>(gsf);
    k_conv_mma<true ><<<dim3(2, 2, 32), 256, SMEM_REQ>>>(pfh, b1, pmh, nullptr, pwh);
    k_conv_mma<false><<<dim3(2, 2, 32), 256, SMEM_REQ>>>(pmh, b2, nullptr, out, pwh + 9*64*64);
}

// round 15
// speedup vs baseline: 1.0617x; 1.0617x over previous
#include <cuda_runtime.h>
#include <cuda_fp16.h>
#include <math.h>
#include <stdint.h>

#define Bv 4
#define Vv 8
#define HW 16384
#define VP 7
#define NBJ 28
#define NIMG 32
typedef unsigned long long u64;
typedef uint32_t u32;

// ------------------------- device scratch -------------------------
__device__ __half g_fh[NIMG*HW*64];   // fused features fp16, NHWC
__device__ __half g_mh[NIMG*HW*64];   // gelu(conv1) fp16, NHWC
__device__ __half g_wh[2*9*64*64];    // [layer][tap][ic][oc] fp16
__device__ int   g_src[NBJ*HW];
__device__ int   g_cnt[NBJ];

// ------------------------- PTX helpers -------------------------
__device__ __forceinline__ u32 s2u(const void* p) {
    u32 a;
    asm("{ .reg .u64 t; cvta.to.shared.u64 t, %1; cvt.u32.u64 %0, t; }" : "=r"(a) : "l"(p));
    return a;
}
__device__ __forceinline__ void ldsm4(u32* r, u32 addr) {
    asm volatile("ldmatrix.sync.aligned.m8n8.x4.shared.b16 {%0,%1,%2,%3}, [%4];"
        : "=r"(r[0]), "=r"(r[1]), "=r"(r[2]), "=r"(r[3]) : "r"(addr));
}
__device__ __forceinline__ void ldsm4t(u32* r, u32 addr) {
    asm volatile("ldmatrix.sync.aligned.m8n8.x4.trans.shared.b16 {%0,%1,%2,%3}, [%4];"
        : "=r"(r[0]), "=r"(r[1]), "=r"(r[2]), "=r"(r[3]) : "r"(addr));
}
__device__ __forceinline__ void mma_fp16(float* d, const u32* a, const u32* b) {
    asm volatile("mma.sync.aligned.m16n8k16.row.col.f32.f16.f16.f32 "
        "{%0,%1,%2,%3}, {%4,%5,%6,%7}, {%8,%9}, {%0,%1,%2,%3};"
        : "+f"(d[0]), "+f"(d[1]), "+f"(d[2]), "+f"(d[3])
        : "r"(a[0]), "r"(a[1]), "r"(a[2]), "r"(a[3]), "r"(b[0]), "r"(b[1]));
}
__device__ __forceinline__ void cp_async16(u32 smem, const void* gptr, int szbytes) {
    asm volatile("cp.async.cg.shared.global [%0], [%1], 16, %2;"
        :: "r"(smem), "l"(gptr), "r"(szbytes) : "memory");
}
#define CP_COMMIT() asm volatile("cp.async.commit_group;" ::: "memory")
#define CP_WAIT0()  asm volatile("cp.async.wait_group 0;" ::: "memory")

// ---------------------------------------------------------------------------
// Kernel 1: geometry (count, camera inline) + weight fp16 convert, one launch.
// ---------------------------------------------------------------------------
__global__ void k_pre(const float* __restrict__ means,
                      const float* __restrict__ intr, const float* __restrict__ extr,
                      const float* __restrict__ w1, const float* __restrict__ w2)
{
    int bid = blockIdx.x;
    if (bid >= 112) {
        int idx = (bid - 112)*256 + threadIdx.x;   // < 73728 exactly
        int layer = idx / 36864; int rem = idx - layer*36864;
        int tap = rem >> 12;
        int ic = (rem >> 6) & 63, oc = rem & 63;
        const float* w = layer ? w2 : w1;
        g_wh[idx] = __float2half(w[(oc*64 + ic)*9 + tap]);
        return;
    }
    int bj = bid >> 2, seg = bid & 3;
    int b = bj / VP, j = bj % VP, k = j + 1;
    __shared__ float cm[24];
    __shared__ int s_cnt;
    if (threadIdx.x == 0) {
        const float* E = extr + (b*Vv + k)*16;
        const float* K = intr + (b*Vv + k)*9;
        float m[16], inv[16];
        #pragma unroll
        for (int i = 0; i < 16; ++i) m[i] = E[i];
        inv[0]  =  m[5]*m[10]*m[15] - m[5]*m[11]*m[14] - m[9]*m[6]*m[15] + m[9]*m[7]*m[14] + m[13]*m[6]*m[11] - m[13]*m[7]*m[10];
        inv[4]  = -m[4]*m[10]*m[15] + m[4]*m[11]*m[14] + m[8]*m[6]*m[15] - m[8]*m[7]*m[14] - m[12]*m[6]*m[11] + m[12]*m[7]*m[10];
        inv[8]  =  m[4]*m[9]*m[15]  - m[4]*m[11]*m[13] - m[8]*m[5]*m[15] + m[8]*m[7]*m[13] + m[12]*m[5]*m[11] - m[12]*m[7]*m[9];
        inv[12] = -m[4]*m[9]*m[14]  + m[4]*m[10]*m[13] + m[8]*m[5]*m[14] - m[8]*m[6]*m[13] - m[12]*m[5]*m[10] + m[12]*m[6]*m[9];
        inv[1]  = -m[1]*m[10]*m[15] + m[1]*m[11]*m[14] + m[9]*m[2]*m[15] - m[9]*m[3]*m[14] - m[13]*m[2]*m[11] + m[13]*m[3]*m[10];
        inv[5]  =  m[0]*m[10]*m[15] - m[0]*m[11]*m[14] - m[8]*m[2]*m[15] + m[8]*m[3]*m[14] + m[12]*m[2]*m[11] - m[12]*m[3]*m[10];
        inv[9]  = -m[0]*m[9]*m[15]  + m[0]*m[11]*m[13] + m[8]*m[1]*m[15] - m[8]*m[3]*m[13] - m[12]*m[1]*m[11] + m[12]*m[3]*m[9];
        inv[13] =  m[0]*m[9]*m[14]  - m[0]*m[10]*m[13] - m[8]*m[1]*m[14] + m[8]*m[2]*m[13] + m[12]*m[1]*m[10] - m[12]*m[2]*m[9];
        inv[2]  =  m[1]*m[6]*m[15]  - m[1]*m[7]*m[14]  - m[5]*m[2]*m[15] + m[5]*m[3]*m[14] + m[13]*m[2]*m[7]  - m[13]*m[3]*m[6];
        inv[6]  = -m[0]*m[6]*m[15]  + m[0]*m[7]*m[14]  + m[4]*m[2]*m[15] - m[4]*m[3]*m[14] - m[12]*m[2]*m[7]  + m[12]*m[3]*m[6];
        inv[10] =  m[0]*m[5]*m[15]  - m[0]*m[7]*m[13]  - m[4]*m[1]*m[15] + m[4]*m[3]*m[13] + m[12]*m[1]*m[7]  - m[12]*m[3]*m[5];
        inv[14] = -m[0]*m[5]*m[14]  + m[0]*m[6]*m[13]  + m[4]*m[1]*m[14] - m[4]*m[2]*m[13] - m[12]*m[1]*m[6]  + m[12]*m[2]*m[5];
        inv[3]  = -m[1]*m[6]*m[11]  + m[1]*m[7]*m[10]  + m[5]*m[2]*m[11] - m[5]*m[3]*m[10] - m[9]*m[2]*m[7]   + m[9]*m[3]*m[6];
        inv[7]  =  m[0]*m[6]*m[11]  - m[0]*m[7]*m[10]  - m[4]*m[2]*m[11] + m[4]*m[3]*m[10] + m[8]*m[2]*m[7]   - m[8]*m[3]*m[6];
        inv[11] = -m[0]*m[5]*m[11]  + m[0]*m[7]*m[9]   + m[4]*m[1]*m[11] - m[4]*m[3]*m[9]  - m[8]*m[1]*m[7]   + m[8]*m[3]*m[5];
        inv[15] =  m[0]*m[5]*m[10]  - m[0]*m[6]*m[9]   - m[4]*m[1]*m[10] + m[4]*m[2]*m[9]  + m[8]*m[1]*m[6]   - m[8]*m[2]*m[5];
        float det = m[0]*inv[0] + m[1]*inv[4] + m[2]*inv[8] + m[3]*inv[12];
        float id = 1.0f / det;
        #pragma unroll
        for (int i = 0; i < 12; ++i) cm[i] = inv[i]*id;
        #pragma unroll
        for (int i = 0; i < 9; ++i) cm[12 + i] = K[i];
        s_cnt = 0;
    }
    __syncthreads();
    const float* mb = means + (size_t)(b*Vv + j)*HW*3;
    int cnt = 0;
    int i0 = seg * 4096;
    for (int i = i0 + threadIdx.x; i < i0 + 4096; i += blockDim.x) {
        float x = mb[i*3+0], y = mb[i*3+1], z = mb[i*3+2];
        float c0 = __fadd_rn(__fadd_rn(__fadd_rn(__fmul_rn(cm[0],x), __fmul_rn(cm[1],y)), __fmul_rn(cm[2],z)), cm[3]);
        float c1 = __fadd_rn(__fadd_rn(__fadd_rn(__fmul_rn(cm[4],x), __fmul_rn(cm[5],y)), __fmul_rn(cm[6],z)), cm[7]);
        float c2 = __fadd_rn(__fadd_rn(__fadd_rn(__fmul_rn(cm[8],x), __fmul_rn(cm[9],y)), __fmul_rn(cm[10],z)), cm[11]);
        float p0 = __fadd_rn(__fadd_rn(__fmul_rn(cm[12],c0), __fmul_rn(cm[13],c1)), __fmul_rn(cm[14],c2));
        float p1 = __fadd_rn(__fadd_rn(__fmul_rn(cm[15],c0), __fmul_rn(cm[16],c1)), __fmul_rn(cm[17],c2));
        float p2 = __fadd_rn(__fadd_rn(__fmul_rn(cm[18],c0), __fmul_rn(cm[19],c1)), __fmul_rn(cm[20],c2));
        float d  = __fadd_rn(p2, 1e-8f);
        float nx = p0 / d, ny = p1 / d;
        bool valid = (nx >= 0.f) && (nx < 1.f) && (ny >= 0.f) && (ny < 1.f) && (c2 > 1e-8f);
        int px = (int)floorf(__fmul_rn(nx, 128.f)); px = min(max(px, 0), 127);
        int py = (int)floorf(__fmul_rn(ny, 128.f)); py = min(max(py, 0), 127);
        g_src[bj*HW + i] = valid ? (py*128 + px) : -1;
        cnt += valid ? 1 : 0;
    }
    atomicAdd(&s_cnt, cnt);
    __syncthreads();
    if (threadIdx.x == 0) atomicAdd(&g_cnt[bj], s_cnt);
}

// ---------------------------------------------------------------------------
// Kernel 2: fuse -> NHWC fp16 (unchanged numerics)
// ---------------------------------------------------------------------------
__global__ __launch_bounds__(256)
void k_fuse2(const float* __restrict__ gsf)
{
    int y = blockIdx.x, n = blockIdx.y;
    int b = n >> 3, view = n & 7;
    __shared__ int S[128];
    __shared__ float s_w;
    int tid = threadIdx.x;
    if (view < VP) {
        int bj = b*VP + view;
        if (tid < 128) S[tid] = g_src[bj*HW + y*128 + tid];
        if (tid == 0) s_w = (0.1f / (float)HW) * (float)g_cnt[bj];
    } else {
        if (tid < 128) S[tid] = -1;
        if (tid == 0) s_w = 0.f;
    }
    __syncthreads();
    float wg = s_w, iw = 1.f / (1.f + wg);
    const float* fj = gsf + ((size_t)n*HW + (size_t)y*128)*64;
    const float* fk = gsf + (size_t)(n+1)*HW*64;
    size_t ob = ((size_t)n*HW + (size_t)y*128)*64;
    #pragma unroll
    for (int i = 0; i < 8; ++i) {
        int idx = tid + i*256;
        int px = idx >> 4, c4 = (idx & 15)*4;
        float4 a = *(const float4*)(fj + px*64 + c4);
        int s = S[px];
        float4 g = make_float4(0.f,0.f,0.f,0.f);
        if (s >= 0) g = *(const float4*)(fk + (size_t)s*64 + c4);
        float v0 = (a.x + g.x*wg)*iw, v1 = (a.y + g.y*wg)*iw;
        float v2 = (a.z + g.z*wg)*iw, v3 = (a.w + g.w*wg)*iw;
        uint2 ph;
        ph.x = (u32)__half_as_ushort(__float2half(v0)) | ((u32)__half_as_ushort(__float2half(v1)) << 16);
        ph.y = (u32)__half_as_ushort(__float2half(v2)) | ((u32)__half_as_ushort(__float2half(v3)) << 16);
        *(uint2*)(g_fh + ob + px*64 + c4) = ph;
    }
}

// ---------------------------------------------------------------------------
// Kernel 3/4: PERSISTENT mma.sync fp16 conv, 2-row iterations (R11 mainloop).
// Grid = 148 blocks x 256 threads; 1024 units of (ochalf, img, 8-row slab),
// static stride-148 schedule -> max 7 units/SM (vs 8 before, 20 SMs idle).
// Per-accumulator MMA order (dx->kc->dy,ar) identical to R11/R12 -> bit-exact.
// SMEM: B 9 tiles stride 80B = 46080B; A ring 6 x 130 x 144B = 112320B.
// ---------------------------------------------------------------------------
#define BTILE 5120u
#define AROW 144u
#define ASLOT 18720u
#define BOFF_SZ 46080u
#define SMEM_REQ 158400
#define NUNITS 1024
#define GRIDC 148

template<bool FIRST>
__global__ void __launch_bounds__(256, 1) k_conv_mma(
    const __half* __restrict__ inh, const float* __restrict__ bias,
    __half* __restrict__ outh, float* __restrict__ outf,
    const __half* __restrict__ wh)
{
    extern __shared__ char dsm[];
    u32 sb = s2u(dsm);
    u32 Boff = sb, Aoff = sb + BOFF_SZ;

    int tid = threadIdx.x, wid = tid >> 5, t = tid & 31;
    int px0 = wid*16;
    u32 laneA = (u32)(t & 15)*AROW + (u32)((t >> 4) << 4);
    u32 laneB = (u32)(t & 15)*80u  + (u32)((t >> 4) << 4);

    int prev_oc = -1;
    float bo0[4], bo1[4];

    for (int u = blockIdx.x; u < NUNITS; u += GRIDC) {
        int ochalf = u >> 9;             // oc-major: B reloads at most twice
        int rem = u & 511;
        int n    = rem >> 4;
        int slab = rem & 15;
        int oc0 = ochalf*32;
        int ybase = slab*8;

        if (ochalf != prev_oc) {
            // previous unit ended with CP_WAIT0 + __syncthreads -> safe to rewrite B
            #pragma unroll
            for (int i = 0; i < 9; ++i) {
                int c = tid + i*256;
                int tap = c >> 8;
                int r2 = c & 255;
                int ic = r2 >> 2, q = r2 & 3;
                uint4 v = *(const uint4*)(wh + ((size_t)tap*64 + ic)*64 + oc0 + q*8);
                *(uint4*)(dsm + (u32)tap*BTILE + (u32)ic*80u + (u32)q*16u) = v;
            }
            #pragma unroll
            for (int nb = 0; nb < 4; ++nb) {
                int oc = oc0 + nb*8 + (t & 3)*2;
                bo0[nb] = bias[oc];
                bo1[nb] = bias[oc + 1];
            }
            prev_oc = ochalf;
        }

        // ---- unit prologue: stage rows ybase-1 .. ybase+2 ----
        #pragma unroll
        for (int rr = 0; rr < 4; ++rr) {
            int r = ybase - 1 + rr;
            bool vr = ((unsigned)r < 128u);
            int rc = vr ? r : 0;
            u32 base = Aoff + (u32)((r + 6) % 6)*ASLOT;
            const __half* gsrc = inh + ((size_t)n*HW + (size_t)rc*128)*64;
            #pragma unroll
            for (int i = 0; i < 5; ++i) {
                int c = tid + i*256;
                if (c < 1040) {
                    int e = c >> 3, q = c & 7;
                    int gpx = e - 1;
                    bool vp = ((unsigned)gpx < 128u);
                    int gpxc = vp ? gpx : 0;
                    cp_async16(base + (u32)e*AROW + (u32)q*16u,
                               gsrc + (size_t)gpxc*64 + q*8, (vr && vp) ? 16 : 0);
                }
            }
        }
        CP_COMMIT();
        CP_WAIT0();
        __syncthreads();

        #pragma unroll 1
        for (int it = 0; it < 4; ++it) {
            int gy = ybase + it*2;
            // ---- stage rows gy+3, gy+4 (overlap with MMA) ----
            #pragma unroll
            for (int rr = 0; rr < 2; ++rr) {
                int r = gy + 3 + rr;
                bool vr = (r <= 127);
                int rc = vr ? r : 127;
                u32 base = Aoff + (u32)((r + 6) % 6)*ASLOT;
                const __half* gsrc = inh + ((size_t)n*HW + (size_t)rc*128)*64;
                #pragma unroll
                for (int i = 0; i < 5; ++i) {
                    int c = tid + i*256;
                    if (c < 1040) {
                        int e = c >> 3, q = c & 7;
                        int gpx = e - 1;
                        bool vp = ((unsigned)gpx < 128u);
                        int gpxc = vp ? gpx : 0;
                        cp_async16(base + (u32)e*AROW + (u32)q*16u,
                                   gsrc + (size_t)gpxc*64 + q*8, (vr && vp) ? 16 : 0);
                    }
                }
            }
            CP_COMMIT();
            // ---- compute rows gy, gy+1 ----
            float acc[2][4][4];
            #pragma unroll
            for (int r = 0; r < 2; ++r)
                #pragma unroll
                for (int nb = 0; nb < 4; ++nb)
                    #pragma unroll
                    for (int i = 0; i < 4; ++i) acc[r][nb][i] = 0.f;

            u32 abase[4];
            #pragma unroll
            for (int ar = 0; ar < 4; ++ar)
                abase[ar] = Aoff + (u32)((gy - 1 + ar + 6) % 6)*ASLOT;

            #pragma unroll
            for (int dx = 0; dx < 3; ++dx) {
                #pragma unroll
                for (int kc = 0; kc < 4; ++kc) {
                    u32 B[3][8];
                    #pragma unroll
                    for (int dy = 0; dy < 3; ++dy) {
                        u32 bb = Boff + (u32)(dy*3 + dx)*BTILE + laneB + (u32)kc*1280u;
                        ldsm4t(B[dy],     bb);
                        ldsm4t(B[dy] + 4, bb + 32u);
                    }
                    #pragma unroll
                    for (int ar = 0; ar < 4; ++ar) {
                        u32 Af[4];
                        ldsm4(Af, abase[ar] + (u32)(px0 + dx)*AROW + laneA + (u32)kc*32u);
                        if (ar < 3) {
                            #pragma unroll
                            for (int nb = 0; nb < 4; ++nb)
                                mma_fp16(acc[0][nb], Af, &B[ar][nb*2]);
                        }
                        if (ar > 0) {
                            #pragma unroll
                            for (int nb = 0; nb < 4; ++nb)
                                mma_fp16(acc[1][nb], Af, &B[ar-1][nb*2]);
                        }
                    }
                }
            }
            // ---- epilogue: bias (+gelu), store rows gy, gy+1 ----
            #pragma unroll
            for (int r = 0; r < 2; ++r) {
                int gyr = gy + r;
                #pragma unroll
                for (int nb = 0; nb < 4; ++nb) {
                    int oc = oc0 + nb*8 + (t & 3)*2;
                    #pragma unroll
                    for (int rg = 0; rg < 2; ++rg) {
                        int px = px0 + (t >> 2) + rg*8;
                        float v0 = acc[r][nb][rg*2]   + bo0[nb];
                        float v1 = acc[r][nb][rg*2+1] + bo1[nb];
                        size_t base = ((size_t)n*HW + (size_t)gyr*128 + px)*64 + oc;
                        if (FIRST) {
                            v0 = 0.5f * v0 * (1.0f + erff(v0 * 0.70710678118654752f));
                            v1 = 0.5f * v1 * (1.0f + erff(v1 * 0.70710678118654752f));
                            u32 hp = (u32)__half_as_ushort(__float2half(v0))
                                   | ((u32)__half_as_ushort(__float2half(v1)) << 16);
                            *(u32*)(outh + base) = hp;
                        } else {
                            *(float2*)(outf + base) = make_float2(v0, v1);
                        }
                    }
                }
            }
            // ---- wait staged rows, single barrier ----
            CP_WAIT0();
            __syncthreads();
        }
    }
}

// ---------------------------------------------------------------------------
extern "C" void kernel_launch(void* const* d_in, const int* in_sizes, int n_in,
                              void* d_out, int out_size)
{
    const float* means = (const float*)d_in[0];
    const float* gsf   = (const float*)d_in[2];
    const float* intr  = (const float*)d_in[3];
    const float* extr  = (const float*)d_in[4];
    const float* w1    = (const float*)d_in[5];
    const float* b1    = (const float*)d_in[6];
    const float* w2    = (const float*)d_in[7];
    const float* b2    = (const float*)d_in[8];
    float* out = (float*)d_out;

    __half *pfh, *pmh, *pwh;
    int* pcnt;
    cudaGetSymbolAddress((void**)&pfh, g_fh);
    cudaGetSymbolAddress((void**)&pmh, g_mh);
    cudaGetSymbolAddress((void**)&pwh, g_wh);
    cudaGetSymbolAddress((void**)&pcnt, g_cnt);

    cudaFuncSetAttribute(k_conv_mma<true>,  cudaFuncAttributeMaxDynamicSharedMemorySize, SMEM_REQ);
    cudaFuncSetAttribute(k_conv_mma<false>, cudaFuncAttributeMaxDynamicSharedMemorySize, SMEM_REQ);

    cudaMemsetAsync(pcnt, 0, NBJ*sizeof(int), 0);
    k_pre<<<400, 256>>>(means, intr, extr, w1, w2);
    k_fuse2<<<dim3(128, 32), 256>>>(gsf);
    k_conv_mma<true ><<<GRIDC, 256, SMEM_REQ>>>(pfh, b1, pmh, nullptr, pwh);
    k_conv_mma<false><<<GRIDC, 256, SMEM_REQ>>>(pmh, b2, nullptr, out, pwh + 9*64*64);
}

// round 16
// speedup vs baseline: 1.0672x; 1.0051x over previous
#include <cuda_runtime.h>
#include <cuda_fp16.h>
#include <math.h>
#include <stdint.h>

#define Bv 4
#define Vv 8
#define HW 16384
#define VP 7
#define NBJ 28
#define NIMG 32
typedef unsigned long long u64;
typedef uint32_t u32;

// ------------------------- device scratch -------------------------
__device__ __half g_fh[NIMG*HW*64];   // fused features fp16, NHWC
__device__ __half g_mh[NIMG*HW*64];   // gelu(conv1) fp16, NHWC
__device__ __half g_wh[2*9*64*64];    // [layer][tap][ic][oc] fp16
__device__ int   g_src[NBJ*HW];
__device__ int   g_cnt[NBJ];

// ------------------------- PTX helpers -------------------------
__device__ __forceinline__ u32 s2u(const void* p) {
    u32 a;
    asm("{ .reg .u64 t; cvta.to.shared.u64 t, %1; cvt.u32.u64 %0, t; }" : "=r"(a) : "l"(p));
    return a;
}
__device__ __forceinline__ void ldsm4(u32* r, u32 addr) {
    asm volatile("ldmatrix.sync.aligned.m8n8.x4.shared.b16 {%0,%1,%2,%3}, [%4];"
        : "=r"(r[0]), "=r"(r[1]), "=r"(r[2]), "=r"(r[3]) : "r"(addr));
}
__device__ __forceinline__ void ldsm4t(u32* r, u32 addr) {
    asm volatile("ldmatrix.sync.aligned.m8n8.x4.trans.shared.b16 {%0,%1,%2,%3}, [%4];"
        : "=r"(r[0]), "=r"(r[1]), "=r"(r[2]), "=r"(r[3]) : "r"(addr));
}
__device__ __forceinline__ void mma_fp16(float* d, const u32* a, const u32* b) {
    asm volatile("mma.sync.aligned.m16n8k16.row.col.f32.f16.f16.f32 "
        "{%0,%1,%2,%3}, {%4,%5,%6,%7}, {%8,%9}, {%0,%1,%2,%3};"
        : "+f"(d[0]), "+f"(d[1]), "+f"(d[2]), "+f"(d[3])
        : "r"(a[0]), "r"(a[1]), "r"(a[2]), "r"(a[3]), "r"(b[0]), "r"(b[1]));
}
__device__ __forceinline__ void cp_async16(u32 smem, const void* gptr, int szbytes) {
    asm volatile("cp.async.cg.shared.global [%0], [%1], 16, %2;"
        :: "r"(smem), "l"(gptr), "r"(szbytes) : "memory");
}
#define CP_COMMIT() asm volatile("cp.async.commit_group;" ::: "memory")
#define CP_WAIT0()  asm volatile("cp.async.wait_group 0;" ::: "memory")

// ---------------------------------------------------------------------------
// Kernel 1: geometry (count, camera inline) + weight fp16 convert, one launch.
// ---------------------------------------------------------------------------
__global__ void k_pre(const float* __restrict__ means,
                      const float* __restrict__ intr, const float* __restrict__ extr,
                      const float* __restrict__ w1, const float* __restrict__ w2)
{
    int bid = blockIdx.x;
    if (bid >= 112) {
        int idx = (bid - 112)*256 + threadIdx.x;   // < 73728 exactly
        int layer = idx / 36864; int rem = idx - layer*36864;
        int tap = rem >> 12;
        int ic = (rem >> 6) & 63, oc = rem & 63;
        const float* w = layer ? w2 : w1;
        g_wh[idx] = __float2half(w[(oc*64 + ic)*9 + tap]);
        return;
    }
    int bj = bid >> 2, seg = bid & 3;
    int b = bj / VP, j = bj % VP, k = j + 1;
    __shared__ float cm[24];
    __shared__ int s_cnt;
    if (threadIdx.x == 0) {
        const float* E = extr + (b*Vv + k)*16;
        const float* K = intr + (b*Vv + k)*9;
        float m[16], inv[16];
        #pragma unroll
        for (int i = 0; i < 16; ++i) m[i] = E[i];
        inv[0]  =  m[5]*m[10]*m[15] - m[5]*m[11]*m[14] - m[9]*m[6]*m[15] + m[9]*m[7]*m[14] + m[13]*m[6]*m[11] - m[13]*m[7]*m[10];
        inv[4]  = -m[4]*m[10]*m[15] + m[4]*m[11]*m[14] + m[8]*m[6]*m[15] - m[8]*m[7]*m[14] - m[12]*m[6]*m[11] + m[12]*m[7]*m[10];
        inv[8]  =  m[4]*m[9]*m[15]  - m[4]*m[11]*m[13] - m[8]*m[5]*m[15] + m[8]*m[7]*m[13] + m[12]*m[5]*m[11] - m[12]*m[7]*m[9];
        inv[12] = -m[4]*m[9]*m[14]  + m[4]*m[10]*m[13] + m[8]*m[5]*m[14] - m[8]*m[6]*m[13] - m[12]*m[5]*m[10] + m[12]*m[6]*m[9];
        inv[1]  = -m[1]*m[10]*m[15] + m[1]*m[11]*m[14] + m[9]*m[2]*m[15] - m[9]*m[3]*m[14] - m[13]*m[2]*m[11] + m[13]*m[3]*m[10];
        inv[5]  =  m[0]*m[10]*m[15] - m[0]*m[11]*m[14] - m[8]*m[2]*m[15] + m[8]*m[3]*m[14] + m[12]*m[2]*m[11] - m[12]*m[3]*m[10];
        inv[9]  = -m[0]*m[9]*m[15]  + m[0]*m[11]*m[13] + m[8]*m[1]*m[15] - m[8]*m[3]*m[13] - m[12]*m[1]*m[11] + m[12]*m[3]*m[9];
        inv[13] =  m[0]*m[9]*m[14]  - m[0]*m[10]*m[13] - m[8]*m[1]*m[14] + m[8]*m[2]*m[13] + m[12]*m[1]*m[10] - m[12]*m[2]*m[9];
        inv[2]  =  m[1]*m[6]*m[15]  - m[1]*m[7]*m[14]  - m[5]*m[2]*m[15] + m[5]*m[3]*m[14] + m[13]*m[2]*m[7]  - m[13]*m[3]*m[6];
        inv[6]  = -m[0]*m[6]*m[15]  + m[0]*m[7]*m[14]  + m[4]*m[2]*m[15] - m[4]*m[3]*m[14] - m[12]*m[2]*m[7]  + m[12]*m[3]*m[6];
        inv[10] =  m[0]*m[5]*m[15]  - m[0]*m[7]*m[13]  - m[4]*m[1]*m[15] + m[4]*m[3]*m[13] + m[12]*m[1]*m[7]  - m[12]*m[3]*m[5];
        inv[14] = -m[0]*m[5]*m[14]  + m[0]*m[6]*m[13]  + m[4]*m[1]*m[14] - m[4]*m[2]*m[13] - m[12]*m[1]*m[6]  + m[12]*m[2]*m[5];
        inv[3]  = -m[1]*m[6]*m[11]  + m[1]*m[7]*m[10]  + m[5]*m[2]*m[11] - m[5]*m[3]*m[10] - m[9]*m[2]*m[7]   + m[9]*m[3]*m[6];
        inv[7]  =  m[0]*m[6]*m[11]  - m[0]*m[7]*m[10]  - m[4]*m[2]*m[11] + m[4]*m[3]*m[10] + m[8]*m[2]*m[7]   - m[8]*m[3]*m[6];
        inv[11] = -m[0]*m[5]*m[11]  + m[0]*m[7]*m[9]   + m[4]*m[1]*m[11] - m[4]*m[3]*m[9]  - m[8]*m[1]*m[7]   + m[8]*m[3]*m[5];
        inv[15] =  m[0]*m[5]*m[10]  - m[0]*m[6]*m[9]   - m[4]*m[1]*m[10] + m[4]*m[2]*m[9]  + m[8]*m[1]*m[6]   - m[8]*m[2]*m[5];
        float det = m[0]*inv[0] + m[1]*inv[4] + m[2]*inv[8] + m[3]*inv[12];
        float id = 1.0f / det;
        #pragma unroll
        for (int i = 0; i < 12; ++i) cm[i] = inv[i]*id;
        #pragma unroll
        for (int i = 0; i < 9; ++i) cm[12 + i] = K[i];
        s_cnt = 0;
    }
    __syncthreads();
    const float* mb = means + (size_t)(b*Vv + j)*HW*3;
    int cnt = 0;
    int i0 = seg * 4096;
    for (int i = i0 + threadIdx.x; i < i0 + 4096; i += blockDim.x) {
        float x = mb[i*3+0], y = mb[i*3+1], z = mb[i*3+2];
        float c0 = __fadd_rn(__fadd_rn(__fadd_rn(__fmul_rn(cm[0],x), __fmul_rn(cm[1],y)), __fmul_rn(cm[2],z)), cm[3]);
        float c1 = __fadd_rn(__fadd_rn(__fadd_rn(__fmul_rn(cm[4],x), __fmul_rn(cm[5],y)), __fmul_rn(cm[6],z)), cm[7]);
        float c2 = __fadd_rn(__fadd_rn(__fadd_rn(__fmul_rn(cm[8],x), __fmul_rn(cm[9],y)), __fmul_rn(cm[10],z)), cm[11]);
        float p0 = __fadd_rn(__fadd_rn(__fmul_rn(cm[12],c0), __fmul_rn(cm[13],c1)), __fmul_rn(cm[14],c2));
        float p1 = __fadd_rn(__fadd_rn(__fmul_rn(cm[15],c0), __fmul_rn(cm[16],c1)), __fmul_rn(cm[17],c2));
        float p2 = __fadd_rn(__fadd_rn(__fmul_rn(cm[18],c0), __fmul_rn(cm[19],c1)), __fmul_rn(cm[20],c2));
        float d  = __fadd_rn(p2, 1e-8f);
        float nx = p0 / d, ny = p1 / d;
        bool valid = (nx >= 0.f) && (nx < 1.f) && (ny >= 0.f) && (ny < 1.f) && (c2 > 1e-8f);
        int px = (int)floorf(__fmul_rn(nx, 128.f)); px = min(max(px, 0), 127);
        int py = (int)floorf(__fmul_rn(ny, 128.f)); py = min(max(py, 0), 127);
        g_src[bj*HW + i] = valid ? (py*128 + px) : -1;
        cnt += valid ? 1 : 0;
    }
    atomicAdd(&s_cnt, cnt);
    __syncthreads();
    if (threadIdx.x == 0) atomicAdd(&g_cnt[bj], s_cnt);
}

// ---------------------------------------------------------------------------
// Kernel 2: fuse -> NHWC fp16 (unchanged numerics)
// ---------------------------------------------------------------------------
__global__ __launch_bounds__(256)
void k_fuse2(const float* __restrict__ gsf)
{
    int y = blockIdx.x, n = blockIdx.y;
    int b = n >> 3, view = n & 7;
    __shared__ int S[128];
    __shared__ float s_w;
    int tid = threadIdx.x;
    if (view < VP) {
        int bj = b*VP + view;
        if (tid < 128) S[tid] = g_src[bj*HW + y*128 + tid];
        if (tid == 0) s_w = (0.1f / (float)HW) * (float)g_cnt[bj];
    } else {
        if (tid < 128) S[tid] = -1;
        if (tid == 0) s_w = 0.f;
    }
    __syncthreads();
    float wg = s_w, iw = 1.f / (1.f + wg);
    const float* fj = gsf + ((size_t)n*HW + (size_t)y*128)*64;
    const float* fk = gsf + (size_t)(n+1)*HW*64;
    size_t ob = ((size_t)n*HW + (size_t)y*128)*64;
    #pragma unroll
    for (int i = 0; i < 8; ++i) {
        int idx = tid + i*256;
        int px = idx >> 4, c4 = (idx & 15)*4;
        float4 a = *(const float4*)(fj + px*64 + c4);
        int s = S[px];
        float4 g = make_float4(0.f,0.f,0.f,0.f);
        if (s >= 0) g = *(const float4*)(fk + (size_t)s*64 + c4);
        float v0 = (a.x + g.x*wg)*iw, v1 = (a.y + g.y*wg)*iw;
        float v2 = (a.z + g.z*wg)*iw, v3 = (a.w + g.w*wg)*iw;
        uint2 ph;
        ph.x = (u32)__half_as_ushort(__float2half(v0)) | ((u32)__half_as_ushort(__float2half(v1)) << 16);
        ph.y = (u32)__half_as_ushort(__float2half(v2)) | ((u32)__half_as_ushort(__float2half(v3)) << 16);
        *(uint2*)(g_fh + ob + px*64 + c4) = ph;
    }
}

// ---------------------------------------------------------------------------
// Kernel 3/4: mma.sync fp16 conv, WARP-INDEPENDENT pipelines.
// grid(2 ochalf, 2 slab, 32 img), 256 threads = 8 warps.
// Each warp owns a 16-px strip + PRIVATE 6-row A ring (18 entries x 144B);
// stages its own halo window via per-thread cp.async; NO block barriers in
// the mainloop (one __syncthreads after the shared B build only).
// Per-accumulator MMA order (dx->kc->dy,ar) identical to R11/R12 -> bit-exact.
// SMEM: B 9 tiles stride 80B = 46080B; A 8 warps x 6 x 18 x 144B = 124416B.
// Total 170496B -> 1 block/SM.
// ---------------------------------------------------------------------------
#define BTILE 5120u
#define AROW 144u
#define AWSLOT 2592u      // 18 entries * 144B
#define AWRING 15552u     // 6 slots
#define BOFF_SZ 46080u
#define SMEM_REQ 170496

template<bool FIRST>
__global__ void __launch_bounds__(256, 1) k_conv_mma(
    const __half* __restrict__ inh, const float* __restrict__ bias,
    __half* __restrict__ outh, float* __restrict__ outf,
    const __half* __restrict__ wh)
{
    extern __shared__ char dsm[];
    u32 sb = s2u(dsm);
    u32 Boff = sb;

    int ochalf = blockIdx.x, slab = blockIdx.y, n = blockIdx.z;
    int oc0 = ochalf*32, ybase = slab*64;
    int tid = threadIdx.x, wid = tid >> 5, t = tid & 31;
    int px0 = wid*16;
    u32 Awarp = sb + BOFF_SZ + (u32)wid*AWRING;

    // ---- B build: 9 tap tiles, stride-80 rows (2304 chunks, all threads) ----
    #pragma unroll
    for (int i = 0; i < 9; ++i) {
        int c = tid + i*256;
        int tap = c >> 8;
        int rem = c & 255;
        int ic = rem >> 2, q = rem & 3;
        uint4 v = *(const uint4*)(wh + ((size_t)tap*64 + ic)*64 + oc0 + q*8);
        *(uint4*)(dsm + (u32)tap*BTILE + (u32)ic*80u + (u32)q*16u) = v;
    }
    // per-thread bias regs
    float bo0[4], bo1[4];
    #pragma unroll
    for (int nb = 0; nb < 4; ++nb) {
        int oc = oc0 + nb*8 + (t & 3)*2;
        bo0[nb] = bias[oc];
        bo1[nb] = bias[oc + 1];
    }
    __syncthreads();   // the ONLY block barrier

    u32 laneA = (u32)(t & 15)*AROW + (u32)((t >> 4) << 4);
    u32 laneB = (u32)(t & 15)*80u  + (u32)((t >> 4) << 4);

    // ---- per-warp prologue: stage rows ybase-1 .. ybase+2 into private ring ----
    #pragma unroll
    for (int rr = 0; rr < 4; ++rr) {
        int r = ybase - 1 + rr;
        bool vr = ((unsigned)r < 128u);
        int rc = vr ? r : 0;
        u32 base = Awarp + (u32)((r + 6) % 6)*AWSLOT;
        const __half* gsrc = inh + ((size_t)n*HW + (size_t)rc*128)*64;
        #pragma unroll
        for (int i = 0; i < 5; ++i) {
            int c = t + i*32;
            if (c < 144) {
                int e = c >> 3, q = c & 7;
                int gpx = px0 + e - 1;
                bool vp = ((unsigned)gpx < 128u);
                int gpxc = vp ? gpx : 0;
                cp_async16(base + (u32)e*AROW + (u32)q*16u,
                           gsrc + (size_t)gpxc*64 + q*8, (vr && vp) ? 16 : 0);
            }
        }
    }
    CP_COMMIT();
    CP_WAIT0();
    __syncwarp();

    #pragma unroll 1
    for (int it = 0; it < 32; ++it) {
        int gy = ybase + it*2;
        // ---- stage rows gy+3, gy+4 into private ring (overlaps MMA) ----
        #pragma unroll
        for (int rr = 0; rr < 2; ++rr) {
            int r = gy + 3 + rr;
            bool vr = (r <= 127);
            int rc = vr ? r : 127;
            u32 base = Awarp + (u32)((r + 6) % 6)*AWSLOT;
            const __half* gsrc = inh + ((size_t)n*HW + (size_t)rc*128)*64;
            #pragma unroll
            for (int i = 0; i < 5; ++i) {
                int c = t + i*32;
                if (c < 144) {
                    int e = c >> 3, q = c & 7;
                    int gpx = px0 + e - 1;
                    bool vp = ((unsigned)gpx < 128u);
                    int gpxc = vp ? gpx : 0;
                    cp_async16(base + (u32)e*AROW + (u32)q*16u,
                               gsrc + (size_t)gpxc*64 + q*8, (vr && vp) ? 16 : 0);
                }
            }
        }
        CP_COMMIT();
        // ---- compute rows gy, gy+1 ----
        float acc[2][4][4];
        #pragma unroll
        for (int r = 0; r < 2; ++r)
            #pragma unroll
            for (int nb = 0; nb < 4; ++nb)
                #pragma unroll
                for (int i = 0; i < 4; ++i) acc[r][nb][i] = 0.f;

        u32 abase[4];
        #pragma unroll
        for (int ar = 0; ar < 4; ++ar)
            abase[ar] = Awarp + (u32)((gy - 1 + ar + 6) % 6)*AWSLOT;

        #pragma unroll
        for (int dx = 0; dx < 3; ++dx) {
            #pragma unroll
            for (int kc = 0; kc < 4; ++kc) {
                u32 B[3][8];
                #pragma unroll
                for (int dy = 0; dy < 3; ++dy) {
                    u32 bb = Boff + (u32)(dy*3 + dx)*BTILE + laneB + (u32)kc*1280u;
                    ldsm4t(B[dy],     bb);
                    ldsm4t(B[dy] + 4, bb + 32u);
                }
                #pragma unroll
                for (int ar = 0; ar < 4; ++ar) {
                    u32 Af[4];
                    ldsm4(Af, abase[ar] + (u32)dx*AROW + laneA + (u32)kc*32u);
                    if (ar < 3) {
                        #pragma unroll
                        for (int nb = 0; nb < 4; ++nb)
                            mma_fp16(acc[0][nb], Af, &B[ar][nb*2]);
                    }
                    if (ar > 0) {
                        #pragma unroll
                        for (int nb = 0; nb < 4; ++nb)
                            mma_fp16(acc[1][nb], Af, &B[ar-1][nb*2]);
                    }
                }
            }
        }
        // ---- epilogue: bias (+gelu), store rows gy, gy+1 ----
        #pragma unroll
        for (int r = 0; r < 2; ++r) {
            int gyr = gy + r;
            #pragma unroll
            for (int nb = 0; nb < 4; ++nb) {
                int oc = oc0 + nb*8 + (t & 3)*2;
                #pragma unroll
                for (int rg = 0; rg < 2; ++rg) {
                    int px = px0 + (t >> 2) + rg*8;
                    float v0 = acc[r][nb][rg*2]   + bo0[nb];
                    float v1 = acc[r][nb][rg*2+1] + bo1[nb];
                    size_t base = ((size_t)n*HW + (size_t)gyr*128 + px)*64 + oc;
                    if (FIRST) {
                        v0 = 0.5f * v0 * (1.0f + erff(v0 * 0.70710678118654752f));
                        v1 = 0.5f * v1 * (1.0f + erff(v1 * 0.70710678118654752f));
                        u32 hp = (u32)__half_as_ushort(__float2half(v0))
                               | ((u32)__half_as_ushort(__float2half(v1)) << 16);
                        *(u32*)(outh + base) = hp;
                    } else {
                        *(float2*)(outf + base) = make_float2(v0, v1);
                    }
                }
            }
        }
        // ---- wait own staged rows; warp-local sync only ----
        CP_WAIT0();
        __syncwarp();
    }
}

// ---------------------------------------------------------------------------
extern "C" void kernel_launch(void* const* d_in, const int* in_sizes, int n_in,
                              void* d_out, int out_size)
{
    const float* means = (const float*)d_in[0];
    const float* gsf   = (const float*)d_in[2];
    const float* intr  = (const float*)d_in[3];
    const float* extr  = (const float*)d_in[4];
    const float* w1    = (const float*)d_in[5];
    const float* b1    = (const float*)d_in[6];
    const float* w2    = (const float*)d_in[7];
    const float* b2    = (const float*)d_in[8];
    float* out = (float*)d_out;

    __half *pfh, *pmh, *pwh;
    int* pcnt;
    cudaGetSymbolAddress((void**)&pfh, g_fh);
    cudaGetSymbolAddress((void**)&pmh, g_mh);
    cudaGetSymbolAddress((void**)&pwh, g_wh);
    cudaGetSymbolAddress((void**)&pcnt, g_cnt);

    cudaFuncSetAttribute(k_conv_mma<true>,  cudaFuncAttributeMaxDynamicSharedMemorySize, SMEM_REQ);
    cudaFuncSetAttribute(k_conv_mma<false>, cudaFuncAttributeMaxDynamicSharedMemorySize, SMEM_REQ);

    cudaMemsetAsync(pcnt, 0, NBJ*sizeof(int), 0);
    k_pre<<<400, 256>>>(means, intr, extr, w1, w2);
    k_fuse2<<<dim3(128, 32), 256>>>(gsf);
    k_conv_mma<true ><<<dim3(2, 2, 32), 256, SMEM_REQ>>>(pfh, b1, pmh, nullptr, pwh);
    k_conv_mma<false><<<dim3(2, 2, 32), 256, SMEM_REQ>>>(pmh, b2, nullptr, out, pwh + 9*64*64);
}